// round 7
// baseline (speedup 1.0000x reference)
#include <cuda_runtime.h>

// OWA pooling: 3x3 / stride 2 / pad(0,1,0,1) over (16,224,224,64) f32 NHWC.
// Per output element: descending-sort the 9 window values, dot with kernel[:,c].
//
// R6: 2 horizontally-adjacent output pixels per thread (shared input column),
// prefetched right-window columns hidden under the left-window sort, and
// 18/25 comparators routed through the hybrid (fma-pipe) compare-exchange.

namespace {

constexpr int B_DIM = 16;
constexpr int H_IN = 224, W_IN = 224;
constexpr int H_OUT = 112, W_OUT = 112;
constexpr int WP = W_OUT / 2;                        // 56 pixel-pairs per row
constexpr int C4 = 16;                               // 64 channels / 4
constexpr int TOTALT = B_DIM * H_OUT * WP * C4;      // 1,605,632 threads
constexpr int BLOCK = 256;

// Pure alu-pipe CAS: 2 FMNMX per lane.
__device__ __forceinline__ void cas4(float4& A, float4& B) {
  float t;
  t = fminf(A.x, B.x); B.x = fmaxf(A.x, B.x); A.x = t;
  t = fminf(A.y, B.y); B.y = fmaxf(A.y, B.y); A.y = t;
  t = fminf(A.z, B.z); B.z = fmaxf(A.z, B.z); A.z = t;
  t = fminf(A.w, B.w); B.w = fmaxf(A.w, B.w); A.w = t;
}

// Hybrid CAS: hi = max(a,b) exact (FMNMX, alu pipe);
//             lo = (a+b) - hi  (2x FADD, fma pipe). lo off by <= 1 ulp of (a+b).
__device__ __forceinline__ void cas4h(float4& A, float4& B) {
  float s, hi;
  s = A.x + B.x; hi = fmaxf(A.x, B.x); B.x = hi; A.x = s - hi;
  s = A.y + B.y; hi = fmaxf(A.y, B.y); B.y = hi; A.y = s - hi;
  s = A.z + B.z; hi = fmaxf(A.z, B.z); B.z = hi; A.z = s - hi;
  s = A.w + B.w; hi = fmaxf(A.w, B.w); B.w = hi; A.w = s - hi;
}

// Published optimal 9-element sorting network: 25 comparators, depth 7.
// 18 routed hybrid (fma-heavy), 7 pure (alu).
__device__ __forceinline__ void sort9(float4 (&v)[9]) {
  cas4h(v[0],v[3]); cas4h(v[1],v[7]); cas4h(v[2],v[5]); cas4h(v[4],v[8]);
  cas4h(v[0],v[7]); cas4h(v[2],v[4]); cas4h(v[3],v[8]); cas4h(v[5],v[6]);
  cas4h(v[0],v[2]); cas4h(v[1],v[3]); cas4h(v[4],v[5]); cas4h(v[7],v[8]);
  cas4h(v[1],v[4]); cas4h(v[3],v[6]); cas4h(v[5],v[7]);
  cas4h(v[0],v[1]); cas4h(v[2],v[4]); cas4h(v[3],v[5]); cas4 (v[6],v[8]);
  cas4 (v[2],v[3]); cas4 (v[4],v[5]); cas4 (v[6],v[7]);
  cas4 (v[1],v[2]); cas4 (v[3],v[4]); cas4 (v[5],v[6]);
}

__device__ __forceinline__ float4 zero4() { return make_float4(0.f,0.f,0.f,0.f); }

} // namespace

__global__ __launch_bounds__(BLOCK, 3)
void owa_pool_kernel(const float4* __restrict__ in4,
                     const float4* __restrict__ wk4,
                     float4* __restrict__ out4) {
  int tid = blockIdx.x * BLOCK + threadIdx.x;
  if (tid >= TOTALT) return;

  int c4  = tid & (C4 - 1);
  int p   = tid >> 4;
  int owp = p % WP;            // pixel-pair index
  int t   = p / WP;
  int oh  = t % H_OUT;
  int b   = t / H_OUT;

  int x0 = owp * 4;            // left window starts at x0; shared col = x0+2
  int y0 = oh * 2;

  // Row validity (only oh==111 has an OOB row) and rightmost col validity.
  bool y2ok = (y0 + 2) < H_IN;
  bool x4ok = (x0 + 4) < W_IN;

  const float4* base = in4 + ((long)b * H_IN) * W_IN * C4 + c4;

  // Left window: columns x0, x0+1, x0+2 -> v0[ky*3+kx]
  float4 v0[9];
#pragma unroll
  for (int ky = 0; ky < 3; ++ky) {
    bool yok = (ky < 2) || y2ok;
    const float4* row = base + (long)(y0 + ky) * W_IN * C4;
#pragma unroll
    for (int kx = 0; kx < 3; ++kx) {
      v0[ky * 3 + kx] = yok ? __ldg(row + (x0 + kx) * C4) : zero4();
    }
  }

  // Save shared column (x0+2) before the in-place sort destroys it.
  float4 s0 = v0[2], s1 = v0[5], s2 = v0[8];

  // Prefetch right-window exclusive columns (x0+3, x0+4); latency hidden
  // under sort9(v0).
  float4 c3[3], c4v[3];
#pragma unroll
  for (int ky = 0; ky < 3; ++ky) {
    bool yok = (ky < 2) || y2ok;
    const float4* row = base + (long)(y0 + ky) * W_IN * C4;
    c3[ky]  = yok          ? __ldg(row + (x0 + 3) * C4) : zero4();
    c4v[ky] = (yok && x4ok) ? __ldg(row + (x0 + 4) * C4) : zero4();
  }

  // ---- pixel 0 ----
  sort9(v0);
  const float4* wkc = wk4 + c4;
  float4 acc = zero4();
#pragma unroll
  for (int k = 0; k < 9; ++k) {   // ascending sort: v[k] is (8-k)-th largest
    float4 w = __ldg(wkc + (8 - k) * C4);
    acc.x = fmaf(v0[k].x, w.x, acc.x);
    acc.y = fmaf(v0[k].y, w.y, acc.y);
    acc.z = fmaf(v0[k].z, w.z, acc.z);
    acc.w = fmaf(v0[k].w, w.w, acc.w);
  }
  int ow0 = owp * 2;
  long obase = (((long)b * H_OUT + oh) * W_OUT + ow0) * C4 + c4;
  out4[obase] = acc;

  // ---- pixel 1: columns x0+2 (shared), x0+3, x0+4 ----
  float4 v1[9];
  v1[0] = s0;     v1[1] = c3[0]; v1[2] = c4v[0];
  v1[3] = s1;     v1[4] = c3[1]; v1[5] = c4v[1];
  v1[6] = s2;     v1[7] = c3[2]; v1[8] = c4v[2];

  sort9(v1);
  float4 acc1 = zero4();
#pragma unroll
  for (int k = 0; k < 9; ++k) {
    float4 w = __ldg(wkc + (8 - k) * C4);
    acc1.x = fmaf(v1[k].x, w.x, acc1.x);
    acc1.y = fmaf(v1[k].y, w.y, acc1.y);
    acc1.z = fmaf(v1[k].z, w.z, acc1.z);
    acc1.w = fmaf(v1[k].w, w.w, acc1.w);
  }
  out4[obase + C4] = acc1;
}

extern "C" void kernel_launch(void* const* d_in, const int* in_sizes, int n_in,
                              void* d_out, int out_size) {
  const float4* in4 = (const float4*)d_in[0];   // (16,224,224,64) f32
  const float4* wk4 = (const float4*)d_in[1];   // (9,64) f32
  float4* out4 = (float4*)d_out;                // (16,112,112,64) f32

  (void)in_sizes; (void)n_in; (void)out_size;
  int grid = (TOTALT + BLOCK - 1) / BLOCK;
  owa_pool_kernel<<<grid, BLOCK>>>(in4, wk4, out4);
}